// round 12
// baseline (speedup 1.0000x reference)
#include <cuda_runtime.h>
#include <math.h>

#define NN   10000
#define GG   200
#define ELn  160000
#define EGn  500000
#define SS   256
#define NAn  16
#define NBn  5

// ---- output offsets (floats) ----
#define OFF_CP   0
#define OFF_CE0  30000
#define OFF_AP   60000
#define OFF_AE   220000
#define OFF_BP   380000
#define OFF_BE   2880000
#define OFF_DL   5380000
#define OFF_RNL  5540000
#define OFF_AG   6020000
#define OFF_RNG  6520000

// ---- tail kernel block partition (128-thread blocks) ----
#define GBLK 2368
#define NS   (GBLK * 4)
#define ABLK 2500
#define LBLK 1250

typedef unsigned long long ull;

// ---- packed f32x2 helpers (sm_103a) ----
__device__ __forceinline__ ull f2pk(float lo, float hi) {
    ull r; asm("mov.b64 %0, {%1, %2};" : "=l"(r) : "f"(lo), "f"(hi)); return r;
}
__device__ __forceinline__ void f2upk(ull v, float& lo, float& hi) {
    asm("mov.b64 {%0, %1}, %2;" : "=f"(lo), "=f"(hi) : "l"(v));
}
__device__ __forceinline__ ull f2fma(ull a, ull b, ull c) {
    ull d; asm("fma.rn.f32x2 %0, %1, %2, %3;" : "=l"(d) : "l"(a), "l"(b), "l"(c)); return d;
}
__device__ __forceinline__ ull f2add(ull a, ull b) {
    ull d; asm("add.rn.f32x2 %0, %1, %2;" : "=l"(d) : "l"(a), "l"(b)); return d;
}

// ---- scratch ----
__device__ float g_sum[GG * 3];
__device__ float g_cnt[GG];
__device__ float g_temb2[GG * SS];
__device__ float g_Wc[NAn * SS];
__device__ float g_hbias[SS];      // 0.5 * b_b0
__device__ float g_posc[NN * 3];
__device__ float g_bufA[NN * SS];
__device__ float g_bufB[NN * SS];

// ============================================================
// Launch 1 — k_pre
// ============================================================
__global__ void __launch_bounds__(256) k_pre(const float* __restrict__ t,
                                             const float* __restrict__ W_time,
                                             const float* __restrict__ b_time,
                                             const float* __restrict__ b_atom,
                                             const float* __restrict__ W_at,
                                             const float* __restrict__ b_at,
                                             const float* __restrict__ W_atom,
                                             const float* __restrict__ b_b0) {
    int b = blockIdx.x;
    int c = threadIdx.x;
    if (b < GG) {
        __shared__ float tin[SS];
        tin[c] = fmaf(t[b], W_time[c], b_time[c]) + b_atom[c];
        __syncthreads();
        float a0 = 0.f, a1 = 0.f, a2 = 0.f, a3 = 0.f;
#pragma unroll 4
        for (int k = 0; k < SS; k += 4) {
            a0 = fmaf(tin[k + 0], W_at[(k + 0) * SS + c], a0);
            a1 = fmaf(tin[k + 1], W_at[(k + 1) * SS + c], a1);
            a2 = fmaf(tin[k + 2], W_at[(k + 2) * SS + c], a2);
            a3 = fmaf(tin[k + 3], W_at[(k + 3) * SS + c], a3);
        }
        g_temb2[b * SS + c] = (a0 + a1) + (a2 + a3) + b_at[c];
    } else if (b < GG + NAn) {
        int r = b - GG;
        __shared__ float arow[SS];
        arow[c] = W_atom[r * SS + c];
        __syncthreads();
        float a0 = 0.f, a1 = 0.f, a2 = 0.f, a3 = 0.f;
#pragma unroll 4
        for (int k = 0; k < SS; k += 4) {
            a0 = fmaf(arow[k + 0], W_at[(k + 0) * SS + c], a0);
            a1 = fmaf(arow[k + 1], W_at[(k + 1) * SS + c], a1);
            a2 = fmaf(arow[k + 2], W_at[(k + 2) * SS + c], a2);
            a3 = fmaf(arow[k + 3], W_at[(k + 3) * SS + c], a3);
        }
        g_Wc[r * SS + c] = (a0 + a1) + (a2 + a3);
    } else {
        g_hbias[c] = 0.5f * b_b0[c];
        for (int i = c; i < GG * 3; i += 256) g_sum[i] = 0.f;
        for (int i = c; i < GG; i += 256)     g_cnt[i] = 0.f;
    }
}

// ============================================================
// Launch 2 — k_possum
// ============================================================
__global__ void k_possum(const float* __restrict__ pos,
                         const int* __restrict__ batch) {
    int n = blockIdx.x * blockDim.x + threadIdx.x;
    if (n >= NN) return;
    int b = batch[n];
    atomicAdd(&g_sum[b * 3 + 0], pos[n * 3 + 0]);
    atomicAdd(&g_sum[b * 3 + 1], pos[n * 3 + 1]);
    atomicAdd(&g_sum[b * 3 + 2], pos[n * 3 + 2]);
    atomicAdd(&g_cnt[b], 1.0f);
}

// ============================================================
// Launch 3 — k_center_h2
// ============================================================
__global__ void __launch_bounds__(256) k_center_h2(const float* __restrict__ pos,
                                                   const int* __restrict__ batch,
                                                   const float* __restrict__ x,
                                                   float* __restrict__ out) {
    if (blockIdx.x < 40) {
        int n = blockIdx.x * 256 + threadIdx.x;
        if (n >= NN) return;
        int b = batch[n];
        float inv = 1.0f / fmaxf(g_cnt[b], 1.0f);
#pragma unroll
        for (int k = 0; k < 3; k++) {
            float v = pos[n * 3 + k] - g_sum[b * 3 + k] * inv;
            g_posc[n * 3 + k] = v;
            out[OFF_CP + n * 3 + k] = v;
            out[OFF_CE0 + n * 3 + k] = 0.f;
        }
    } else {
        int n = blockIdx.x - 40;
        int c = threadIdx.x;
        __shared__ float xs[NAn];
        __shared__ int bsh;
        if (c < NAn) xs[c] = x[n * NAn + c];
        if (c == 0) bsh = batch[n];
        __syncthreads();
        float acc = g_temb2[bsh * SS + c];
#pragma unroll
        for (int k = 0; k < NAn; k++) acc = fmaf(xs[k], g_Wc[k * SS + c], acc);
        g_bufA[n * SS + c] = acc;
    }
}

// ============================================================
// Launches 4,5 — fp32 GEMM, 64x128 tile, BK=16, double-buffered,
// 128 threads, 8x8 micro-tile, packed row-pair FFMA2.
// ACT: 0 = bias only, 1 = bias + silu
// ============================================================
template <int ACT>
__global__ void __launch_bounds__(128) k_gemm64(const float* __restrict__ A,
                                                const float* __restrict__ W,
                                                const float* __restrict__ bias,
                                                float* __restrict__ C) {
    __shared__ float As[2][16][68];   // [k][row], pad keeps 16B alignment
    __shared__ float Bs[2][16][128];
    const int tid = threadIdx.x;
    const int row0 = blockIdx.y * 64;
    const int col0 = blockIdx.x * 128;
    const int ar = tid >> 1;            // 0..63 (A row)
    const int ak = (tid & 1) * 8;       // 0 or 8 (A k-offset, 2x float4)
    const int bk = tid >> 3;            // 0..15 (B k-row)
    const int bc = (tid & 7) * 16;      // 0..112 (B col, 4x float4)
    const int ty = tid >> 4;            // 0..7  (8 rows each)
    const int tx = tid & 15;            // 0..15 (8 cols split 4+4)
    const int arow = row0 + ar;

    // prologue: tile 0 -> buf 0
    {
        float4 a0 = make_float4(0.f, 0.f, 0.f, 0.f), a1 = a0;
        if (arow < NN) {
            a0 = *(const float4*)&A[(size_t)arow * SS + ak];
            a1 = *(const float4*)&A[(size_t)arow * SS + ak + 4];
        }
        As[0][ak + 0][ar] = a0.x; As[0][ak + 1][ar] = a0.y;
        As[0][ak + 2][ar] = a0.z; As[0][ak + 3][ar] = a0.w;
        As[0][ak + 4][ar] = a1.x; As[0][ak + 5][ar] = a1.y;
        As[0][ak + 6][ar] = a1.z; As[0][ak + 7][ar] = a1.w;
#pragma unroll
        for (int q = 0; q < 4; q++)
            *(float4*)&Bs[0][bk][bc + q * 4] =
                *(const float4*)&W[(size_t)bk * SS + col0 + bc + q * 4];
    }
    __syncthreads();

    ull accp[4][8];   // [row-pair m][col j]: rows ty*8+2m, ty*8+2m+1
#pragma unroll
    for (int m = 0; m < 4; m++)
#pragma unroll
        for (int j = 0; j < 8; j++) accp[m][j] = 0ull;

    for (int k0 = 0; k0 < SS; k0 += 16) {
        const int buf = (k0 >> 4) & 1;
        const bool more = (k0 + 16 < SS);
        float4 na0 = make_float4(0.f, 0.f, 0.f, 0.f), na1 = na0;
        float4 nb[4];
        if (more) {
            if (arow < NN) {
                na0 = *(const float4*)&A[(size_t)arow * SS + k0 + 16 + ak];
                na1 = *(const float4*)&A[(size_t)arow * SS + k0 + 16 + ak + 4];
            }
#pragma unroll
            for (int q = 0; q < 4; q++)
                nb[q] = *(const float4*)&W[(size_t)(k0 + 16 + bk) * SS + col0 + bc + q * 4];
        }
#pragma unroll
        for (int k = 0; k < 16; k++) {
            // a: 4 packed row-pairs (rows ty*8..ty*8+7), naturally packed
            ulonglong2 ap01 = *(const ulonglong2*)&As[buf][k][ty * 8];
            ulonglong2 ap23 = *(const ulonglong2*)&As[buf][k][ty * 8 + 4];
            float b[8];
            *(float4*)&b[0] = *(const float4*)&Bs[buf][k][tx * 4];
            *(float4*)&b[4] = *(const float4*)&Bs[buf][k][64 + tx * 4];
            ull ap[4] = {ap01.x, ap01.y, ap23.x, ap23.y};
#pragma unroll
            for (int j = 0; j < 8; j++) {
                ull bd = f2pk(b[j], b[j]);
                accp[0][j] = f2fma(ap[0], bd, accp[0][j]);
                accp[1][j] = f2fma(ap[1], bd, accp[1][j]);
                accp[2][j] = f2fma(ap[2], bd, accp[2][j]);
                accp[3][j] = f2fma(ap[3], bd, accp[3][j]);
            }
        }
        if (more) {
            As[buf ^ 1][ak + 0][ar] = na0.x; As[buf ^ 1][ak + 1][ar] = na0.y;
            As[buf ^ 1][ak + 2][ar] = na0.z; As[buf ^ 1][ak + 3][ar] = na0.w;
            As[buf ^ 1][ak + 4][ar] = na1.x; As[buf ^ 1][ak + 5][ar] = na1.y;
            As[buf ^ 1][ak + 6][ar] = na1.z; As[buf ^ 1][ak + 7][ar] = na1.w;
#pragma unroll
            for (int q = 0; q < 4; q++)
                *(float4*)&Bs[buf ^ 1][bk][bc + q * 4] = nb[q];
            __syncthreads();
        }
    }

#pragma unroll
    for (int m = 0; m < 4; m++) {
#pragma unroll
        for (int s = 0; s < 2; s++) {
            int row = row0 + ty * 8 + 2 * m + s;
            if (row >= NN) continue;
#pragma unroll
            for (int half = 0; half < 2; half++) {
                int col = col0 + half * 64 + tx * 4;
                float4 v;
                float lo, hi;
                f2upk(accp[m][half * 4 + 0], lo, hi); v.x = s ? hi : lo;
                f2upk(accp[m][half * 4 + 1], lo, hi); v.y = s ? hi : lo;
                f2upk(accp[m][half * 4 + 2], lo, hi); v.z = s ? hi : lo;
                f2upk(accp[m][half * 4 + 3], lo, hi); v.w = s ? hi : lo;
                v.x += bias[col + 0];
                v.y += bias[col + 1];
                v.z += bias[col + 2];
                v.w += bias[col + 3];
                if (ACT == 1) {
                    v.x = __fdividef(v.x, 1.0f + __expf(-v.x));
                    v.y = __fdividef(v.y, 1.0f + __expf(-v.y));
                    v.z = __fdividef(v.z, 1.0f + __expf(-v.z));
                    v.w = __fdividef(v.w, 1.0f + __expf(-v.w));
                }
                *(float4*)&C[(size_t)row * SS + col] = v;
            }
        }
    }
}

// ============================================================
// Launch 6 — k_tail (fused, 128-thread blocks):
//   global edges: packed f32x2 MLP, split butterfly reduction,
//   idx prefetch 2 ahead, u/pos prefetch 1 ahead
// ============================================================
__global__ void __launch_bounds__(128, 3) k_tail(const int* __restrict__ eig,
                                                 const float* __restrict__ u,
                                                 const float* __restrict__ W_b0,
                                                 const float* __restrict__ W_b1,
                                                 const float* __restrict__ b_b1,
                                                 const float* __restrict__ h3,
                                                 const float* __restrict__ W_atoms,
                                                 const float* __restrict__ b_atoms,
                                                 const int* __restrict__ eil,
                                                 float* __restrict__ out) {
    const int blk = blockIdx.x;
    const int tid = threadIdx.x;
    const int lane = tid & 31;

    if (blk < GBLK) {
        // ---------------- global edges ----------------
        const int slot = blk * 4 + (tid >> 5);
        const int ch0 = lane * 8;

        ull wb1p[8][5];
        float wd[8];
#pragma unroll
        for (int k = 0; k < 8; k++) {
            wd[k] = W_b0[SS * SS + ch0 + k];
#pragma unroll
            for (int m = 0; m < 5; m++)
                wb1p[k][m] = f2pk(W_b1[(ch0 + k) * 10 + 2 * m],
                                  W_b1[(ch0 + k) * 10 + 2 * m + 1]);
        }
        float bb[5];
        {
            int base = (lane < 16) ? 0 : 5;
#pragma unroll
            for (int g = 0; g < 5; g++) bb[g] = b_b1[base + g];
        }

        int e = slot;
        if (e >= EGn) return;
        int j1 = eig[e];
        int i1 = eig[EGn + e];
        ulonglong2 UA0 = *(const ulonglong2*)(u + (size_t)i1 * SS + ch0);
        ulonglong2 UA1 = *(const ulonglong2*)(u + (size_t)i1 * SS + ch0 + 4);
        ulonglong2 UC0 = *(const ulonglong2*)(u + (size_t)j1 * SS + ch0);
        ulonglong2 UC1 = *(const ulonglong2*)(u + (size_t)j1 * SS + ch0 + 4);
        float pix1 = g_posc[i1 * 3 + 0], piy1 = g_posc[i1 * 3 + 1], piz1 = g_posc[i1 * 3 + 2];
        float pjx1 = g_posc[j1 * 3 + 0], pjy1 = g_posc[j1 * 3 + 1], pjz1 = g_posc[j1 * 3 + 2];
        int e2 = e + NS;
        int j2 = 0, i2 = 0;
        if (e2 < EGn) { j2 = eig[e2]; i2 = eig[EGn + e2]; }

        while (e < EGn) {
            int e3 = e2 + NS;
            int j3 = 0, i3 = 0;
            if (e3 < EGn) { j3 = eig[e3]; i3 = eig[EGn + e3]; }
            ulonglong2 UB0 = make_ulonglong2(0, 0), UB1 = UB0, UD0 = UB0, UD1 = UB0;
            float pix2 = 0.f, piy2 = 0.f, piz2 = 0.f, pjx2 = 0.f, pjy2 = 0.f, pjz2 = 0.f;
            if (e2 < EGn) {
                UB0 = *(const ulonglong2*)(u + (size_t)i2 * SS + ch0);
                UB1 = *(const ulonglong2*)(u + (size_t)i2 * SS + ch0 + 4);
                UD0 = *(const ulonglong2*)(u + (size_t)j2 * SS + ch0);
                UD1 = *(const ulonglong2*)(u + (size_t)j2 * SS + ch0 + 4);
                pix2 = g_posc[i2 * 3 + 0]; piy2 = g_posc[i2 * 3 + 1]; piz2 = g_posc[i2 * 3 + 2];
                pjx2 = g_posc[j2 * 3 + 0]; pjy2 = g_posc[j2 * 3 + 1]; pjz2 = g_posc[j2 * 3 + 2];
            }

            float rx = pix1 - pjx1, ry = piy1 - pjy1, rz = piz1 - pjz1;
            float ss = rx * rx + ry * ry + rz * rz;
            float db = sqrtf(ss);
            if (lane == 0) {
                out[OFF_AG + e] = pix1 * pjx1 + piy1 * pjy1 + piz1 * pjz1;
                float inv = rsqrtf(fmaxf(ss, 1e-6f));
                out[OFF_RNG + 3 * e + 0] = rx * inv;
                out[OFF_RNG + 3 * e + 1] = ry * inv;
                out[OFF_RNG + 3 * e + 2] = rz * inv;
            }

            ull hp[4];
            hp[0] = f2add(UA0.x, UC0.x);
            hp[1] = f2add(UA0.y, UC0.y);
            hp[2] = f2add(UA1.x, UC1.x);
            hp[3] = f2add(UA1.y, UC1.y);
            float h[8];
            f2upk(hp[0], h[0], h[1]);
            f2upk(hp[1], h[2], h[3]);
            f2upk(hp[2], h[4], h[5]);
            f2upk(hp[3], h[6], h[7]);

            ull accp[5] = {0ull, 0ull, 0ull, 0ull, 0ull};
#pragma unroll
            for (int k = 0; k < 8; k++) {
                float pre = fmaf(db, wd[k], h[k]);
                float hv = __fdividef(pre, 1.0f + __expf(-pre));
                ull hvp = f2pk(hv, hv);
#pragma unroll
                for (int m = 0; m < 5; m++) accp[m] = f2fma(hvp, wb1p[k][m], accp[m]);
            }

            float acc[10];
#pragma unroll
            for (int m = 0; m < 5; m++) f2upk(accp[m], acc[2 * m], acc[2 * m + 1]);

            // round 1: butterfly off=16 (all 10)
#pragma unroll
            for (int o = 0; o < 10; o++)
                acc[o] += __shfl_xor_sync(0xffffffffu, acc[o], 16);
            // split: lanes<16 reduce outputs 0..4, lanes>=16 reduce 5..9
            float v[5];
#pragma unroll
            for (int g = 0; g < 5; g++) v[g] = (lane < 16) ? acc[g] : acc[g + 5];
#pragma unroll
            for (int off = 8; off > 0; off >>= 1) {
#pragma unroll
                for (int g = 0; g < 5; g++)
                    v[g] += __shfl_xor_sync(0xffffffffu, v[g], off);
            }
            if (lane == 0) {
#pragma unroll
                for (int g = 0; g < 5; g++)
                    out[OFF_BP + (size_t)e * 5 + g] = v[g] + bb[g];
            } else if (lane == 16) {
#pragma unroll
                for (int g = 0; g < 5; g++)
                    out[OFF_BE + (size_t)e * 5 + g] = v[g] + bb[g];
            }

            e = e2; i1 = i2; j1 = j2;
            UA0 = UB0; UA1 = UB1; UC0 = UD0; UC1 = UD1;
            pix1 = pix2; piy1 = piy2; piz1 = piz2;
            pjx1 = pjx2; pjy1 = pjy2; pjz1 = pjz2;
            e2 = e3; i2 = i3; j2 = j3;
        }
    } else if (blk < GBLK + ABLK) {
        // ---------------- atoms ----------------
        int w = (blk - GBLK) * 4 + (tid >> 5);
        if (w >= NN) return;
        float acc = b_atoms[lane];
        for (int k0 = 0; k0 < SS; k0 += 32) {
            float hv = h3[(size_t)w * SS + k0 + lane];
#pragma unroll
            for (int kk = 0; kk < 32; kk++) {
                float h = __shfl_sync(0xffffffffu, hv, kk);
                acc = fmaf(h, W_atoms[(k0 + kk) * 32 + lane], acc);
            }
        }
        if (lane < NAn) out[OFF_AE + w * NAn + lane] = acc;
        else            out[OFF_AP + w * NAn + (lane - NAn)] = acc;
    } else {
        // ---------------- local edges ----------------
        int e = (blk - GBLK - ABLK) * 128 + tid;
        if (e >= ELn) return;
        int s = eil[e];
        int tg = eil[ELn + e];
        float rx = g_posc[tg * 3 + 0] - g_posc[s * 3 + 0];
        float ry = g_posc[tg * 3 + 1] - g_posc[s * 3 + 1];
        float rz = g_posc[tg * 3 + 2] - g_posc[s * 3 + 2];
        float ss = rx * rx + ry * ry + rz * rz;
        float sc = fmaxf(ss, 1e-6f);
        float d = sqrtf(sc);
        out[OFF_DL + e] = d;
        float inv = rsqrtf(sc);
        out[OFF_RNL + 3 * e + 0] = rx * inv;
        out[OFF_RNL + 3 * e + 1] = ry * inv;
        out[OFF_RNL + 3 * e + 2] = rz * inv;
    }
}

// ============================================================
// Host launcher
// ============================================================
extern "C" void kernel_launch(void* const* d_in, const int* in_sizes, int n_in,
                              void* d_out, int out_size) {
    int iX, iT, iPOS, iWT, iBT, iWA, iBA, iWAT, iBAT, iWSH, iBSH,
        iWB0, iBB0, iWB1, iBB1, iWATM, iBATM, iEIL, iEIG, iBATCH;
    if (in_sizes[3] == 2 * ELn) {
        iX = 0; iT = 1; iPOS = 2; iEIL = 3; iEIG = 4; iBATCH = 6;
        iWT = 7; iBT = 8; iWA = 9; iBA = 10; iWAT = 11; iBAT = 12;
        iWSH = 13; iBSH = 14; iWB0 = 15; iBB0 = 16; iWB1 = 17; iBB1 = 18;
        iWATM = 20; iBATM = 21;
    } else {
        iX = 0; iT = 1; iPOS = 2; iWT = 4; iBT = 5; iWA = 6; iBA = 7;
        iWAT = 8; iBAT = 9; iWSH = 10; iBSH = 11; iWB0 = 12; iBB0 = 13;
        iWB1 = 14; iBB1 = 15; iWATM = 17; iBATM = 18;
        iEIL = 19; iEIG = 20; iBATCH = 21;
    }

    const float* x       = (const float*)d_in[iX];
    const float* t       = (const float*)d_in[iT];
    const float* pos     = (const float*)d_in[iPOS];
    const float* W_time  = (const float*)d_in[iWT];
    const float* b_time  = (const float*)d_in[iBT];
    const float* W_atom  = (const float*)d_in[iWA];
    const float* b_atom  = (const float*)d_in[iBA];
    const float* W_at    = (const float*)d_in[iWAT];
    const float* b_at    = (const float*)d_in[iBAT];
    const float* W_sh    = (const float*)d_in[iWSH];
    const float* b_sh    = (const float*)d_in[iBSH];
    const float* W_b0    = (const float*)d_in[iWB0];
    const float* b_b0    = (const float*)d_in[iBB0];
    const float* W_b1    = (const float*)d_in[iWB1];
    const float* b_b1    = (const float*)d_in[iBB1];
    const float* W_atoms = (const float*)d_in[iWATM];
    const float* b_atoms = (const float*)d_in[iBATM];
    const int* eil       = (const int*)d_in[iEIL];
    const int* eig       = (const int*)d_in[iEIG];
    const int* batch     = (const int*)d_in[iBATCH];
    float* out = (float*)d_out;

    float *bufA, *bufB, *hbias;
    cudaGetSymbolAddress((void**)&bufA, g_bufA);
    cudaGetSymbolAddress((void**)&bufB, g_bufB);
    cudaGetSymbolAddress((void**)&hbias, g_hbias);

    // 1
    k_pre<<<GG + NAn + 1, 256>>>(t, W_time, b_time, b_atom, W_at, b_at, W_atom, b_b0);
    // 2
    k_possum<<<(NN + 255) / 256, 256>>>(pos, batch);
    // 3
    k_center_h2<<<40 + NN, 256>>>(pos, batch, x, out);
    // 4,5
    dim3 gg(2, (NN + 63) / 64);   // (2, 157)
    k_gemm64<1><<<gg, 128>>>(bufA, W_sh, b_sh, bufB);      // h3 -> bufB
    k_gemm64<0><<<gg, 128>>>(bufB, W_b0, hbias, bufA);     // u + 0.5*b_b0 -> bufA
    // 6 — fused tail
    k_tail<<<GBLK + ABLK + LBLK, 128>>>(eig, bufA, W_b0, W_b1, b_b1,
                                        bufB, W_atoms, b_atoms, eil, out);
}

// round 13
// speedup vs baseline: 1.6161x; 1.6161x over previous
#include <cuda_runtime.h>
#include <math.h>

#define NN   10000
#define GG   200
#define ELn  160000
#define EGn  500000
#define SS   256
#define NAn  16
#define NBn  5

// ---- output offsets (floats) ----
#define OFF_CP   0
#define OFF_CE0  30000
#define OFF_AP   60000
#define OFF_AE   220000
#define OFF_BP   380000
#define OFF_BE   2880000
#define OFF_DL   5380000
#define OFF_RNL  5540000
#define OFF_AG   6020000
#define OFF_RNG  6520000

// ---- tail kernel block partition (128-thread blocks) ----
#define GBLK 2368
#define NS   (GBLK * 4)
#define ABLK 2500
// local edges now ride along with GEMM<1>: 313 extra grid rows x 512 edges
#define LROWS 313

typedef unsigned long long ull;

// ---- packed f32x2 helpers (sm_103a) ----
__device__ __forceinline__ ull f2pk(float lo, float hi) {
    ull r; asm("mov.b64 %0, {%1, %2};" : "=l"(r) : "f"(lo), "f"(hi)); return r;
}
__device__ __forceinline__ void f2upk(ull v, float& lo, float& hi) {
    asm("mov.b64 {%0, %1}, %2;" : "=f"(lo), "=f"(hi) : "l"(v));
}
__device__ __forceinline__ ull f2fma(ull a, ull b, ull c) {
    ull d; asm("fma.rn.f32x2 %0, %1, %2, %3;" : "=l"(d) : "l"(a), "l"(b), "l"(c)); return d;
}
__device__ __forceinline__ ull f2add(ull a, ull b) {
    ull d; asm("add.rn.f32x2 %0, %1, %2;" : "=l"(d) : "l"(a), "l"(b)); return d;
}

// ---- scratch ----
__device__ float g_sum[GG * 3];
__device__ float g_cnt[GG];
__device__ float g_temb2[GG * SS];
__device__ float g_Wc[NAn * SS];
__device__ float g_hbias[SS];      // 0.5 * b_b0
__device__ float g_posc[NN * 3];
__device__ float g_bufA[NN * SS];
__device__ float g_bufB[NN * SS];

// ============================================================
// Launch 1 — k_pre
// ============================================================
__global__ void __launch_bounds__(256) k_pre(const float* __restrict__ t,
                                             const float* __restrict__ W_time,
                                             const float* __restrict__ b_time,
                                             const float* __restrict__ b_atom,
                                             const float* __restrict__ W_at,
                                             const float* __restrict__ b_at,
                                             const float* __restrict__ W_atom,
                                             const float* __restrict__ b_b0) {
    int b = blockIdx.x;
    int c = threadIdx.x;
    if (b < GG) {
        __shared__ float tin[SS];
        tin[c] = fmaf(t[b], W_time[c], b_time[c]) + b_atom[c];
        __syncthreads();
        float a0 = 0.f, a1 = 0.f, a2 = 0.f, a3 = 0.f;
#pragma unroll 4
        for (int k = 0; k < SS; k += 4) {
            a0 = fmaf(tin[k + 0], W_at[(k + 0) * SS + c], a0);
            a1 = fmaf(tin[k + 1], W_at[(k + 1) * SS + c], a1);
            a2 = fmaf(tin[k + 2], W_at[(k + 2) * SS + c], a2);
            a3 = fmaf(tin[k + 3], W_at[(k + 3) * SS + c], a3);
        }
        g_temb2[b * SS + c] = (a0 + a1) + (a2 + a3) + b_at[c];
    } else if (b < GG + NAn) {
        int r = b - GG;
        __shared__ float arow[SS];
        arow[c] = W_atom[r * SS + c];
        __syncthreads();
        float a0 = 0.f, a1 = 0.f, a2 = 0.f, a3 = 0.f;
#pragma unroll 4
        for (int k = 0; k < SS; k += 4) {
            a0 = fmaf(arow[k + 0], W_at[(k + 0) * SS + c], a0);
            a1 = fmaf(arow[k + 1], W_at[(k + 1) * SS + c], a1);
            a2 = fmaf(arow[k + 2], W_at[(k + 2) * SS + c], a2);
            a3 = fmaf(arow[k + 3], W_at[(k + 3) * SS + c], a3);
        }
        g_Wc[r * SS + c] = (a0 + a1) + (a2 + a3);
    } else {
        g_hbias[c] = 0.5f * b_b0[c];
        for (int i = c; i < GG * 3; i += 256) g_sum[i] = 0.f;
        for (int i = c; i < GG; i += 256)     g_cnt[i] = 0.f;
    }
}

// ============================================================
// Launch 2 — k_possum
// ============================================================
__global__ void k_possum(const float* __restrict__ pos,
                         const int* __restrict__ batch) {
    int n = blockIdx.x * blockDim.x + threadIdx.x;
    if (n >= NN) return;
    int b = batch[n];
    atomicAdd(&g_sum[b * 3 + 0], pos[n * 3 + 0]);
    atomicAdd(&g_sum[b * 3 + 1], pos[n * 3 + 1]);
    atomicAdd(&g_sum[b * 3 + 2], pos[n * 3 + 2]);
    atomicAdd(&g_cnt[b], 1.0f);
}

// ============================================================
// Launch 3 — k_center_h2
// ============================================================
__global__ void __launch_bounds__(256) k_center_h2(const float* __restrict__ pos,
                                                   const int* __restrict__ batch,
                                                   const float* __restrict__ x,
                                                   float* __restrict__ out) {
    if (blockIdx.x < 40) {
        int n = blockIdx.x * 256 + threadIdx.x;
        if (n >= NN) return;
        int b = batch[n];
        float inv = 1.0f / fmaxf(g_cnt[b], 1.0f);
#pragma unroll
        for (int k = 0; k < 3; k++) {
            float v = pos[n * 3 + k] - g_sum[b * 3 + k] * inv;
            g_posc[n * 3 + k] = v;
            out[OFF_CP + n * 3 + k] = v;
            out[OFF_CE0 + n * 3 + k] = 0.f;
        }
    } else {
        int n = blockIdx.x - 40;
        int c = threadIdx.x;
        __shared__ float xs[NAn];
        __shared__ int bsh;
        if (c < NAn) xs[c] = x[n * NAn + c];
        if (c == 0) bsh = batch[n];
        __syncthreads();
        float acc = g_temb2[bsh * SS + c];
#pragma unroll
        for (int k = 0; k < NAn; k++) acc = fmaf(xs[k], g_Wc[k * SS + c], acc);
        g_bufA[n * SS + c] = acc;
    }
}

// ============================================================
// Launches 4,5 — fp32 GEMM (R10-proven 256-thread config):
// 64x128 tile, BK=16, double-buffered, packed f32x2 inner loop.
// ACT: 0 = bias only, 1 = bias + silu
// LOCALW: 1 = extra grid rows (blockIdx.y >= 157) process local edges
// ============================================================
template <int ACT, int LOCALW>
__global__ void __launch_bounds__(256) k_gemm64(const float* __restrict__ A,
                                                const float* __restrict__ W,
                                                const float* __restrict__ bias,
                                                float* __restrict__ C,
                                                const int* __restrict__ eil,
                                                float* __restrict__ out) {
    if (LOCALW && blockIdx.y >= 157) {
        // ---------------- local edge attrs (piggyback blocks) ----------------
        int e = (blockIdx.y - 157) * 512 + blockIdx.x * 256 + threadIdx.x;
        if (e >= ELn) return;
        int s = eil[e];
        int tg = eil[ELn + e];
        float rx = g_posc[tg * 3 + 0] - g_posc[s * 3 + 0];
        float ry = g_posc[tg * 3 + 1] - g_posc[s * 3 + 1];
        float rz = g_posc[tg * 3 + 2] - g_posc[s * 3 + 2];
        float ss = rx * rx + ry * ry + rz * rz;
        float sc = fmaxf(ss, 1e-6f);
        out[OFF_DL + e] = sqrtf(sc);
        float inv = rsqrtf(sc);
        out[OFF_RNL + 3 * e + 0] = rx * inv;
        out[OFF_RNL + 3 * e + 1] = ry * inv;
        out[OFF_RNL + 3 * e + 2] = rz * inv;
        return;
    }

    __shared__ float As[2][16][68];
    __shared__ float Bs[2][16][128];
    const int tid = threadIdx.x;
    const int row0 = blockIdx.y * 64;
    const int col0 = blockIdx.x * 128;
    const int ar = tid >> 2;            // 0..63 (A row)
    const int ak = (tid & 3) * 4;       // 0,4,8,12 (A k-offset, float4)
    const int bk = tid >> 4;            // 0..15 (B k-row)
    const int bc = (tid & 15) * 8;      // 0..120 (B col, 2x float4)
    const int ty = tid >> 4;            // 0..15 (4 rows)
    const int tx = tid & 15;            // 0..15 (8 cols split 4+4)
    const int arow = row0 + ar;

    {
        float4 av = make_float4(0.f, 0.f, 0.f, 0.f);
        if (arow < NN) av = *(const float4*)&A[(size_t)arow * SS + ak];
        As[0][ak + 0][ar] = av.x;
        As[0][ak + 1][ar] = av.y;
        As[0][ak + 2][ar] = av.z;
        As[0][ak + 3][ar] = av.w;
        *(float4*)&Bs[0][bk][bc]     = *(const float4*)&W[(size_t)bk * SS + col0 + bc];
        *(float4*)&Bs[0][bk][bc + 4] = *(const float4*)&W[(size_t)bk * SS + col0 + bc + 4];
    }
    __syncthreads();

    ull accp[4][4];
#pragma unroll
    for (int i = 0; i < 4; i++)
#pragma unroll
        for (int m = 0; m < 4; m++) accp[i][m] = 0ull;

    for (int k0 = 0; k0 < SS; k0 += 16) {
        const int buf = (k0 >> 4) & 1;
        const bool more = (k0 + 16 < SS);
        float4 nav = make_float4(0.f, 0.f, 0.f, 0.f);
        float4 nbv0, nbv1;
        if (more) {
            if (arow < NN) nav = *(const float4*)&A[(size_t)arow * SS + k0 + 16 + ak];
            nbv0 = *(const float4*)&W[(size_t)(k0 + 16 + bk) * SS + col0 + bc];
            nbv1 = *(const float4*)&W[(size_t)(k0 + 16 + bk) * SS + col0 + bc + 4];
        }
#pragma unroll
        for (int k = 0; k < 16; k++) {
            float4 a4 = *(const float4*)&As[buf][k][ty * 4];
            ulonglong2 b01 = *(const ulonglong2*)&Bs[buf][k][tx * 4];
            ulonglong2 b23 = *(const ulonglong2*)&Bs[buf][k][64 + tx * 4];
            ull ap0 = f2pk(a4.x, a4.x);
            ull ap1 = f2pk(a4.y, a4.y);
            ull ap2 = f2pk(a4.z, a4.z);
            ull ap3 = f2pk(a4.w, a4.w);
            accp[0][0] = f2fma(ap0, b01.x, accp[0][0]);
            accp[0][1] = f2fma(ap0, b01.y, accp[0][1]);
            accp[0][2] = f2fma(ap0, b23.x, accp[0][2]);
            accp[0][3] = f2fma(ap0, b23.y, accp[0][3]);
            accp[1][0] = f2fma(ap1, b01.x, accp[1][0]);
            accp[1][1] = f2fma(ap1, b01.y, accp[1][1]);
            accp[1][2] = f2fma(ap1, b23.x, accp[1][2]);
            accp[1][3] = f2fma(ap1, b23.y, accp[1][3]);
            accp[2][0] = f2fma(ap2, b01.x, accp[2][0]);
            accp[2][1] = f2fma(ap2, b01.y, accp[2][1]);
            accp[2][2] = f2fma(ap2, b23.x, accp[2][2]);
            accp[2][3] = f2fma(ap2, b23.y, accp[2][3]);
            accp[3][0] = f2fma(ap3, b01.x, accp[3][0]);
            accp[3][1] = f2fma(ap3, b01.y, accp[3][1]);
            accp[3][2] = f2fma(ap3, b23.x, accp[3][2]);
            accp[3][3] = f2fma(ap3, b23.y, accp[3][3]);
        }
        if (more) {
            As[buf ^ 1][ak + 0][ar] = nav.x;
            As[buf ^ 1][ak + 1][ar] = nav.y;
            As[buf ^ 1][ak + 2][ar] = nav.z;
            As[buf ^ 1][ak + 3][ar] = nav.w;
            *(float4*)&Bs[buf ^ 1][bk][bc]     = nbv0;
            *(float4*)&Bs[buf ^ 1][bk][bc + 4] = nbv1;
            __syncthreads();
        }
    }

#pragma unroll
    for (int i = 0; i < 4; i++) {
        int row = row0 + ty * 4 + i;
        if (row >= NN) continue;
#pragma unroll
        for (int half = 0; half < 2; half++) {
            int col = col0 + half * 64 + tx * 4;
            float4 v;
            f2upk(accp[i][half * 2 + 0], v.x, v.y);
            f2upk(accp[i][half * 2 + 1], v.z, v.w);
            v.x += bias[col + 0];
            v.y += bias[col + 1];
            v.z += bias[col + 2];
            v.w += bias[col + 3];
            if (ACT == 1) {
                v.x = __fdividef(v.x, 1.0f + __expf(-v.x));
                v.y = __fdividef(v.y, 1.0f + __expf(-v.y));
                v.z = __fdividef(v.z, 1.0f + __expf(-v.z));
                v.w = __fdividef(v.w, 1.0f + __expf(-v.w));
            }
            *(float4*)&C[(size_t)row * SS + col] = v;
        }
    }
}

// ============================================================
// Launch 6 — k_tail (fused, 128-thread blocks):
//   global edges: packed f32x2 MLP, split butterfly reduction,
//   idx prefetch 2 ahead, u/pos prefetch 1 ahead; then atoms
// ============================================================
__global__ void __launch_bounds__(128, 3) k_tail(const int* __restrict__ eig,
                                                 const float* __restrict__ u,
                                                 const float* __restrict__ W_b0,
                                                 const float* __restrict__ W_b1,
                                                 const float* __restrict__ b_b1,
                                                 const float* __restrict__ h3,
                                                 const float* __restrict__ W_atoms,
                                                 const float* __restrict__ b_atoms,
                                                 float* __restrict__ out) {
    const int blk = blockIdx.x;
    const int tid = threadIdx.x;
    const int lane = tid & 31;

    if (blk < GBLK) {
        // ---------------- global edges ----------------
        const int slot = blk * 4 + (tid >> 5);
        const int ch0 = lane * 8;

        ull wb1p[8][5];
        float wd[8];
#pragma unroll
        for (int k = 0; k < 8; k++) {
            wd[k] = W_b0[SS * SS + ch0 + k];
#pragma unroll
            for (int m = 0; m < 5; m++)
                wb1p[k][m] = f2pk(W_b1[(ch0 + k) * 10 + 2 * m],
                                  W_b1[(ch0 + k) * 10 + 2 * m + 1]);
        }
        float bb[5];
        {
            int base = (lane < 16) ? 0 : 5;
#pragma unroll
            for (int g = 0; g < 5; g++) bb[g] = b_b1[base + g];
        }

        int e = slot;
        if (e >= EGn) return;
        int j1 = eig[e];
        int i1 = eig[EGn + e];
        ulonglong2 UA0 = *(const ulonglong2*)(u + (size_t)i1 * SS + ch0);
        ulonglong2 UA1 = *(const ulonglong2*)(u + (size_t)i1 * SS + ch0 + 4);
        ulonglong2 UC0 = *(const ulonglong2*)(u + (size_t)j1 * SS + ch0);
        ulonglong2 UC1 = *(const ulonglong2*)(u + (size_t)j1 * SS + ch0 + 4);
        float pix1 = g_posc[i1 * 3 + 0], piy1 = g_posc[i1 * 3 + 1], piz1 = g_posc[i1 * 3 + 2];
        float pjx1 = g_posc[j1 * 3 + 0], pjy1 = g_posc[j1 * 3 + 1], pjz1 = g_posc[j1 * 3 + 2];
        int e2 = e + NS;
        int j2 = 0, i2 = 0;
        if (e2 < EGn) { j2 = eig[e2]; i2 = eig[EGn + e2]; }

        while (e < EGn) {
            int e3 = e2 + NS;
            int j3 = 0, i3 = 0;
            if (e3 < EGn) { j3 = eig[e3]; i3 = eig[EGn + e3]; }
            ulonglong2 UB0 = make_ulonglong2(0, 0), UB1 = UB0, UD0 = UB0, UD1 = UB0;
            float pix2 = 0.f, piy2 = 0.f, piz2 = 0.f, pjx2 = 0.f, pjy2 = 0.f, pjz2 = 0.f;
            if (e2 < EGn) {
                UB0 = *(const ulonglong2*)(u + (size_t)i2 * SS + ch0);
                UB1 = *(const ulonglong2*)(u + (size_t)i2 * SS + ch0 + 4);
                UD0 = *(const ulonglong2*)(u + (size_t)j2 * SS + ch0);
                UD1 = *(const ulonglong2*)(u + (size_t)j2 * SS + ch0 + 4);
                pix2 = g_posc[i2 * 3 + 0]; piy2 = g_posc[i2 * 3 + 1]; piz2 = g_posc[i2 * 3 + 2];
                pjx2 = g_posc[j2 * 3 + 0]; pjy2 = g_posc[j2 * 3 + 1]; pjz2 = g_posc[j2 * 3 + 2];
            }

            float rx = pix1 - pjx1, ry = piy1 - pjy1, rz = piz1 - pjz1;
            float ss = rx * rx + ry * ry + rz * rz;
            float db = sqrtf(ss);
            if (lane == 0) {
                out[OFF_AG + e] = pix1 * pjx1 + piy1 * pjy1 + piz1 * pjz1;
                float inv = rsqrtf(fmaxf(ss, 1e-6f));
                out[OFF_RNG + 3 * e + 0] = rx * inv;
                out[OFF_RNG + 3 * e + 1] = ry * inv;
                out[OFF_RNG + 3 * e + 2] = rz * inv;
            }

            ull hp[4];
            hp[0] = f2add(UA0.x, UC0.x);
            hp[1] = f2add(UA0.y, UC0.y);
            hp[2] = f2add(UA1.x, UC1.x);
            hp[3] = f2add(UA1.y, UC1.y);
            float h[8];
            f2upk(hp[0], h[0], h[1]);
            f2upk(hp[1], h[2], h[3]);
            f2upk(hp[2], h[4], h[5]);
            f2upk(hp[3], h[6], h[7]);

            ull accp[5] = {0ull, 0ull, 0ull, 0ull, 0ull};
#pragma unroll
            for (int k = 0; k < 8; k++) {
                float pre = fmaf(db, wd[k], h[k]);
                float hv = __fdividef(pre, 1.0f + __expf(-pre));
                ull hvp = f2pk(hv, hv);
#pragma unroll
                for (int m = 0; m < 5; m++) accp[m] = f2fma(hvp, wb1p[k][m], accp[m]);
            }

            float acc[10];
#pragma unroll
            for (int m = 0; m < 5; m++) f2upk(accp[m], acc[2 * m], acc[2 * m + 1]);

#pragma unroll
            for (int o = 0; o < 10; o++)
                acc[o] += __shfl_xor_sync(0xffffffffu, acc[o], 16);
            float v[5];
#pragma unroll
            for (int g = 0; g < 5; g++) v[g] = (lane < 16) ? acc[g] : acc[g + 5];
#pragma unroll
            for (int off = 8; off > 0; off >>= 1) {
#pragma unroll
                for (int g = 0; g < 5; g++)
                    v[g] += __shfl_xor_sync(0xffffffffu, v[g], off);
            }
            if (lane == 0) {
#pragma unroll
                for (int g = 0; g < 5; g++)
                    out[OFF_BP + (size_t)e * 5 + g] = v[g] + bb[g];
            } else if (lane == 16) {
#pragma unroll
                for (int g = 0; g < 5; g++)
                    out[OFF_BE + (size_t)e * 5 + g] = v[g] + bb[g];
            }

            e = e2; i1 = i2; j1 = j2;
            UA0 = UB0; UA1 = UB1; UC0 = UD0; UC1 = UD1;
            pix1 = pix2; piy1 = piy2; piz1 = piz2;
            pjx1 = pjx2; pjy1 = pjy2; pjz1 = pjz2;
            e2 = e3; i2 = i3; j2 = j3;
        }
    } else {
        // ---------------- atoms ----------------
        int w = (blk - GBLK) * 4 + (tid >> 5);
        if (w >= NN) return;
        float acc = b_atoms[lane];
        for (int k0 = 0; k0 < SS; k0 += 32) {
            float hv = h3[(size_t)w * SS + k0 + lane];
#pragma unroll
            for (int kk = 0; kk < 32; kk++) {
                float h = __shfl_sync(0xffffffffu, hv, kk);
                acc = fmaf(h, W_atoms[(k0 + kk) * 32 + lane], acc);
            }
        }
        if (lane < NAn) out[OFF_AE + w * NAn + lane] = acc;
        else            out[OFF_AP + w * NAn + (lane - NAn)] = acc;
    }
}

// ============================================================
// Host launcher
// ============================================================
extern "C" void kernel_launch(void* const* d_in, const int* in_sizes, int n_in,
                              void* d_out, int out_size) {
    int iX, iT, iPOS, iWT, iBT, iWA, iBA, iWAT, iBAT, iWSH, iBSH,
        iWB0, iBB0, iWB1, iBB1, iWATM, iBATM, iEIL, iEIG, iBATCH;
    if (in_sizes[3] == 2 * ELn) {
        iX = 0; iT = 1; iPOS = 2; iEIL = 3; iEIG = 4; iBATCH = 6;
        iWT = 7; iBT = 8; iWA = 9; iBA = 10; iWAT = 11; iBAT = 12;
        iWSH = 13; iBSH = 14; iWB0 = 15; iBB0 = 16; iWB1 = 17; iBB1 = 18;
        iWATM = 20; iBATM = 21;
    } else {
        iX = 0; iT = 1; iPOS = 2; iWT = 4; iBT = 5; iWA = 6; iBA = 7;
        iWAT = 8; iBAT = 9; iWSH = 10; iBSH = 11; iWB0 = 12; iBB0 = 13;
        iWB1 = 14; iBB1 = 15; iWATM = 17; iBATM = 18;
        iEIL = 19; iEIG = 20; iBATCH = 21;
    }

    const float* x       = (const float*)d_in[iX];
    const float* t       = (const float*)d_in[iT];
    const float* pos     = (const float*)d_in[iPOS];
    const float* W_time  = (const float*)d_in[iWT];
    const float* b_time  = (const float*)d_in[iBT];
    const float* W_atom  = (const float*)d_in[iWA];
    const float* b_atom  = (const float*)d_in[iBA];
    const float* W_at    = (const float*)d_in[iWAT];
    const float* b_at    = (const float*)d_in[iBAT];
    const float* W_sh    = (const float*)d_in[iWSH];
    const float* b_sh    = (const float*)d_in[iBSH];
    const float* W_b0    = (const float*)d_in[iWB0];
    const float* b_b0    = (const float*)d_in[iBB0];
    const float* W_b1    = (const float*)d_in[iWB1];
    const float* b_b1    = (const float*)d_in[iBB1];
    const float* W_atoms = (const float*)d_in[iWATM];
    const float* b_atoms = (const float*)d_in[iBATM];
    const int* eil       = (const int*)d_in[iEIL];
    const int* eig       = (const int*)d_in[iEIG];
    const int* batch     = (const int*)d_in[iBATCH];
    float* out = (float*)d_out;

    float *bufA, *bufB, *hbias;
    cudaGetSymbolAddress((void**)&bufA, g_bufA);
    cudaGetSymbolAddress((void**)&bufB, g_bufB);
    cudaGetSymbolAddress((void**)&hbias, g_hbias);

    // 1
    k_pre<<<GG + NAn + 1, 256>>>(t, W_time, b_time, b_atom, W_at, b_at, W_atom, b_b0);
    // 2
    k_possum<<<(NN + 255) / 256, 256>>>(pos, batch);
    // 3
    k_center_h2<<<40 + NN, 256>>>(pos, batch, x, out);
    // 4: h3 GEMM + piggybacked local edges
    dim3 gg1(2, 157 + LROWS);
    k_gemm64<1, 1><<<gg1, 256>>>(bufA, W_sh, b_sh, bufB, eil, out);
    // 5: u GEMM
    dim3 gg0(2, 157);
    k_gemm64<0, 0><<<gg0, 256>>>(bufB, W_b0, hbias, bufA, eil, out);
    // 6 — fused tail (global edges + atoms)
    k_tail<<<GBLK + ABLK, 128>>>(eig, bufA, W_b0, W_b1, b_b1,
                                 bufB, W_atoms, b_atoms, out);
}

// round 14
// speedup vs baseline: 1.8225x; 1.1277x over previous
#include <cuda_runtime.h>
#include <math.h>

#define NN   10000
#define GG   200
#define ELn  160000
#define EGn  500000
#define SS   256
#define NAn  16
#define NBn  5

// ---- output offsets (floats) ----
#define OFF_CP   0
#define OFF_CE0  30000
#define OFF_AP   60000
#define OFF_AE   220000
#define OFF_BP   380000
#define OFF_BE   2880000
#define OFF_DL   5380000
#define OFF_RNL  5540000
#define OFF_AG   6020000
#define OFF_RNG  6520000

// ---- tail kernel block partition (128-thread blocks) ----
#define GBLK 2368
#define NS   (GBLK * 4)
#define ABLK 2500
#define LROWS 313     // local-edge rows on GEMM<1>
#define GROWS 977     // geometry rows on GEMM<0> (977*512 >= 500000)

typedef unsigned long long ull;

// ---- packed f32x2 helpers (sm_103a) ----
__device__ __forceinline__ ull f2pk(float lo, float hi) {
    ull r; asm("mov.b64 %0, {%1, %2};" : "=l"(r) : "f"(lo), "f"(hi)); return r;
}
__device__ __forceinline__ void f2upk(ull v, float& lo, float& hi) {
    asm("mov.b64 {%0, %1}, %2;" : "=f"(lo), "=f"(hi) : "l"(v));
}
__device__ __forceinline__ ull f2fma(ull a, ull b, ull c) {
    ull d; asm("fma.rn.f32x2 %0, %1, %2, %3;" : "=l"(d) : "l"(a), "l"(b), "l"(c)); return d;
}
__device__ __forceinline__ ull f2add(ull a, ull b) {
    ull d; asm("add.rn.f32x2 %0, %1, %2;" : "=l"(d) : "l"(a), "l"(b)); return d;
}

// ---- scratch ----
__device__ float g_sum[GG * 3];
__device__ float g_cnt[GG];
__device__ float g_temb2[GG * SS];
__device__ float g_Wc[NAn * SS];
__device__ float g_hbias[SS];      // 0.5 * b_b0
__device__ float g_posc[NN * 3];
__device__ float g_db[EGn];        // per-global-edge distance (for bonds MLP)
__device__ float g_bufA[NN * SS];
__device__ float g_bufB[NN * SS];

// ============================================================
// Launch 1 — k_pre
// ============================================================
__global__ void __launch_bounds__(256) k_pre(const float* __restrict__ t,
                                             const float* __restrict__ W_time,
                                             const float* __restrict__ b_time,
                                             const float* __restrict__ b_atom,
                                             const float* __restrict__ W_at,
                                             const float* __restrict__ b_at,
                                             const float* __restrict__ W_atom,
                                             const float* __restrict__ b_b0) {
    int b = blockIdx.x;
    int c = threadIdx.x;
    if (b < GG) {
        __shared__ float tin[SS];
        tin[c] = fmaf(t[b], W_time[c], b_time[c]) + b_atom[c];
        __syncthreads();
        float a0 = 0.f, a1 = 0.f, a2 = 0.f, a3 = 0.f;
#pragma unroll 4
        for (int k = 0; k < SS; k += 4) {
            a0 = fmaf(tin[k + 0], W_at[(k + 0) * SS + c], a0);
            a1 = fmaf(tin[k + 1], W_at[(k + 1) * SS + c], a1);
            a2 = fmaf(tin[k + 2], W_at[(k + 2) * SS + c], a2);
            a3 = fmaf(tin[k + 3], W_at[(k + 3) * SS + c], a3);
        }
        g_temb2[b * SS + c] = (a0 + a1) + (a2 + a3) + b_at[c];
    } else if (b < GG + NAn) {
        int r = b - GG;
        __shared__ float arow[SS];
        arow[c] = W_atom[r * SS + c];
        __syncthreads();
        float a0 = 0.f, a1 = 0.f, a2 = 0.f, a3 = 0.f;
#pragma unroll 4
        for (int k = 0; k < SS; k += 4) {
            a0 = fmaf(arow[k + 0], W_at[(k + 0) * SS + c], a0);
            a1 = fmaf(arow[k + 1], W_at[(k + 1) * SS + c], a1);
            a2 = fmaf(arow[k + 2], W_at[(k + 2) * SS + c], a2);
            a3 = fmaf(arow[k + 3], W_at[(k + 3) * SS + c], a3);
        }
        g_Wc[r * SS + c] = (a0 + a1) + (a2 + a3);
    } else {
        g_hbias[c] = 0.5f * b_b0[c];
        for (int i = c; i < GG * 3; i += 256) g_sum[i] = 0.f;
        for (int i = c; i < GG; i += 256)     g_cnt[i] = 0.f;
    }
}

// ============================================================
// Launch 2 — k_possum
// ============================================================
__global__ void k_possum(const float* __restrict__ pos,
                         const int* __restrict__ batch) {
    int n = blockIdx.x * blockDim.x + threadIdx.x;
    if (n >= NN) return;
    int b = batch[n];
    atomicAdd(&g_sum[b * 3 + 0], pos[n * 3 + 0]);
    atomicAdd(&g_sum[b * 3 + 1], pos[n * 3 + 1]);
    atomicAdd(&g_sum[b * 3 + 2], pos[n * 3 + 2]);
    atomicAdd(&g_cnt[b], 1.0f);
}

// ============================================================
// Launch 3 — k_center_h2
// ============================================================
__global__ void __launch_bounds__(256) k_center_h2(const float* __restrict__ pos,
                                                   const int* __restrict__ batch,
                                                   const float* __restrict__ x,
                                                   float* __restrict__ out) {
    if (blockIdx.x < 40) {
        int n = blockIdx.x * 256 + threadIdx.x;
        if (n >= NN) return;
        int b = batch[n];
        float inv = 1.0f / fmaxf(g_cnt[b], 1.0f);
#pragma unroll
        for (int k = 0; k < 3; k++) {
            float v = pos[n * 3 + k] - g_sum[b * 3 + k] * inv;
            g_posc[n * 3 + k] = v;
            out[OFF_CP + n * 3 + k] = v;
            out[OFF_CE0 + n * 3 + k] = 0.f;
        }
    } else {
        int n = blockIdx.x - 40;
        int c = threadIdx.x;
        __shared__ float xs[NAn];
        __shared__ int bsh;
        if (c < NAn) xs[c] = x[n * NAn + c];
        if (c == 0) bsh = batch[n];
        __syncthreads();
        float acc = g_temb2[bsh * SS + c];
#pragma unroll
        for (int k = 0; k < NAn; k++) acc = fmaf(xs[k], g_Wc[k * SS + c], acc);
        g_bufA[n * SS + c] = acc;
    }
}

// ============================================================
// Launches 4,5 — fp32 GEMM (256-thread, 64x128, BK=16, dbl-buffer,
// packed f32x2). WORK: 0 none, 1 local-edge overlay, 2 geometry overlay.
// ============================================================
template <int ACT, int WORK>
__global__ void __launch_bounds__(256) k_gemm64(const float* __restrict__ A,
                                                const float* __restrict__ W,
                                                const float* __restrict__ bias,
                                                float* __restrict__ C,
                                                const int* __restrict__ eil,
                                                const int* __restrict__ eig,
                                                float* __restrict__ out) {
    if (WORK == 1 && blockIdx.y >= 157) {
        // ---- local edge attrs overlay ----
        int e = (blockIdx.y - 157) * 512 + blockIdx.x * 256 + threadIdx.x;
        if (e >= ELn) return;
        int s = eil[e];
        int tg = eil[ELn + e];
        float rx = g_posc[tg * 3 + 0] - g_posc[s * 3 + 0];
        float ry = g_posc[tg * 3 + 1] - g_posc[s * 3 + 1];
        float rz = g_posc[tg * 3 + 2] - g_posc[s * 3 + 2];
        float ss = rx * rx + ry * ry + rz * rz;
        float sc = fmaxf(ss, 1e-6f);
        out[OFF_DL + e] = sqrtf(sc);
        float inv = rsqrtf(sc);
        out[OFF_RNL + 3 * e + 0] = rx * inv;
        out[OFF_RNL + 3 * e + 1] = ry * inv;
        out[OFF_RNL + 3 * e + 2] = rz * inv;
        return;
    }
    if (WORK == 2 && blockIdx.y >= 157) {
        // ---- global edge geometry overlay: a_g, rn_g, d -> g_db ----
        int e = (blockIdx.y - 157) * 512 + blockIdx.x * 256 + threadIdx.x;
        if (e >= EGn) return;
        int j = eig[e];
        int i = eig[EGn + e];
        float pix = g_posc[i * 3 + 0], piy = g_posc[i * 3 + 1], piz = g_posc[i * 3 + 2];
        float pjx = g_posc[j * 3 + 0], pjy = g_posc[j * 3 + 1], pjz = g_posc[j * 3 + 2];
        float rx = pix - pjx, ry = piy - pjy, rz = piz - pjz;
        float ss = rx * rx + ry * ry + rz * rz;
        g_db[e] = sqrtf(ss);
        out[OFF_AG + e] = pix * pjx + piy * pjy + piz * pjz;
        float inv = rsqrtf(fmaxf(ss, 1e-6f));
        out[OFF_RNG + 3 * e + 0] = rx * inv;
        out[OFF_RNG + 3 * e + 1] = ry * inv;
        out[OFF_RNG + 3 * e + 2] = rz * inv;
        return;
    }

    __shared__ float As[2][16][68];
    __shared__ float Bs[2][16][128];
    const int tid = threadIdx.x;
    const int row0 = blockIdx.y * 64;
    const int col0 = blockIdx.x * 128;
    const int ar = tid >> 2;
    const int ak = (tid & 3) * 4;
    const int bk = tid >> 4;
    const int bc = (tid & 15) * 8;
    const int ty = tid >> 4;
    const int tx = tid & 15;
    const int arow = row0 + ar;

    {
        float4 av = make_float4(0.f, 0.f, 0.f, 0.f);
        if (arow < NN) av = *(const float4*)&A[(size_t)arow * SS + ak];
        As[0][ak + 0][ar] = av.x;
        As[0][ak + 1][ar] = av.y;
        As[0][ak + 2][ar] = av.z;
        As[0][ak + 3][ar] = av.w;
        *(float4*)&Bs[0][bk][bc]     = *(const float4*)&W[(size_t)bk * SS + col0 + bc];
        *(float4*)&Bs[0][bk][bc + 4] = *(const float4*)&W[(size_t)bk * SS + col0 + bc + 4];
    }
    __syncthreads();

    ull accp[4][4];
#pragma unroll
    for (int i = 0; i < 4; i++)
#pragma unroll
        for (int m = 0; m < 4; m++) accp[i][m] = 0ull;

    for (int k0 = 0; k0 < SS; k0 += 16) {
        const int buf = (k0 >> 4) & 1;
        const bool more = (k0 + 16 < SS);
        float4 nav = make_float4(0.f, 0.f, 0.f, 0.f);
        float4 nbv0, nbv1;
        if (more) {
            if (arow < NN) nav = *(const float4*)&A[(size_t)arow * SS + k0 + 16 + ak];
            nbv0 = *(const float4*)&W[(size_t)(k0 + 16 + bk) * SS + col0 + bc];
            nbv1 = *(const float4*)&W[(size_t)(k0 + 16 + bk) * SS + col0 + bc + 4];
        }
#pragma unroll
        for (int k = 0; k < 16; k++) {
            float4 a4 = *(const float4*)&As[buf][k][ty * 4];
            ulonglong2 b01 = *(const ulonglong2*)&Bs[buf][k][tx * 4];
            ulonglong2 b23 = *(const ulonglong2*)&Bs[buf][k][64 + tx * 4];
            ull ap0 = f2pk(a4.x, a4.x);
            ull ap1 = f2pk(a4.y, a4.y);
            ull ap2 = f2pk(a4.z, a4.z);
            ull ap3 = f2pk(a4.w, a4.w);
            accp[0][0] = f2fma(ap0, b01.x, accp[0][0]);
            accp[0][1] = f2fma(ap0, b01.y, accp[0][1]);
            accp[0][2] = f2fma(ap0, b23.x, accp[0][2]);
            accp[0][3] = f2fma(ap0, b23.y, accp[0][3]);
            accp[1][0] = f2fma(ap1, b01.x, accp[1][0]);
            accp[1][1] = f2fma(ap1, b01.y, accp[1][1]);
            accp[1][2] = f2fma(ap1, b23.x, accp[1][2]);
            accp[1][3] = f2fma(ap1, b23.y, accp[1][3]);
            accp[2][0] = f2fma(ap2, b01.x, accp[2][0]);
            accp[2][1] = f2fma(ap2, b01.y, accp[2][1]);
            accp[2][2] = f2fma(ap2, b23.x, accp[2][2]);
            accp[2][3] = f2fma(ap2, b23.y, accp[2][3]);
            accp[3][0] = f2fma(ap3, b01.x, accp[3][0]);
            accp[3][1] = f2fma(ap3, b01.y, accp[3][1]);
            accp[3][2] = f2fma(ap3, b23.x, accp[3][2]);
            accp[3][3] = f2fma(ap3, b23.y, accp[3][3]);
        }
        if (more) {
            As[buf ^ 1][ak + 0][ar] = nav.x;
            As[buf ^ 1][ak + 1][ar] = nav.y;
            As[buf ^ 1][ak + 2][ar] = nav.z;
            As[buf ^ 1][ak + 3][ar] = nav.w;
            *(float4*)&Bs[buf ^ 1][bk][bc]     = nbv0;
            *(float4*)&Bs[buf ^ 1][bk][bc + 4] = nbv1;
            __syncthreads();
        }
    }

#pragma unroll
    for (int i = 0; i < 4; i++) {
        int row = row0 + ty * 4 + i;
        if (row >= NN) continue;
#pragma unroll
        for (int half = 0; half < 2; half++) {
            int col = col0 + half * 64 + tx * 4;
            float4 v;
            f2upk(accp[i][half * 2 + 0], v.x, v.y);
            f2upk(accp[i][half * 2 + 1], v.z, v.w);
            v.x += bias[col + 0];
            v.y += bias[col + 1];
            v.z += bias[col + 2];
            v.w += bias[col + 3];
            if (ACT == 1) {
                v.x = __fdividef(v.x, 1.0f + __expf(-v.x));
                v.y = __fdividef(v.y, 1.0f + __expf(-v.y));
                v.z = __fdividef(v.z, 1.0f + __expf(-v.z));
                v.w = __fdividef(v.w, 1.0f + __expf(-v.w));
            }
            *(float4*)&C[(size_t)row * SS + col] = v;
        }
    }
}

// ============================================================
// Launch 6 — k_tail: global-edge bonds MLP (geometry precomputed)
//   + atoms. Packed f32x2, paired-rcp sigmoid, split reduction,
//   idx prefetch 2 ahead, u/db prefetch 1 ahead.
// ============================================================
__global__ void __launch_bounds__(128, 3) k_tail(const int* __restrict__ eig,
                                                 const float* __restrict__ u,
                                                 const float* __restrict__ W_b0,
                                                 const float* __restrict__ W_b1,
                                                 const float* __restrict__ b_b1,
                                                 const float* __restrict__ h3,
                                                 const float* __restrict__ W_atoms,
                                                 const float* __restrict__ b_atoms,
                                                 float* __restrict__ out) {
    const int blk = blockIdx.x;
    const int tid = threadIdx.x;
    const int lane = tid & 31;

    if (blk < GBLK) {
        // ---------------- global edges (bonds MLP only) ----------------
        const int slot = blk * 4 + (tid >> 5);
        const int ch0 = lane * 8;

        ull wb1p[8][5];
        ull wdp[4];
#pragma unroll
        for (int m = 0; m < 4; m++)
            wdp[m] = f2pk(W_b0[SS * SS + ch0 + 2 * m], W_b0[SS * SS + ch0 + 2 * m + 1]);
#pragma unroll
        for (int k = 0; k < 8; k++)
#pragma unroll
            for (int m = 0; m < 5; m++)
                wb1p[k][m] = f2pk(W_b1[(ch0 + k) * 10 + 2 * m],
                                  W_b1[(ch0 + k) * 10 + 2 * m + 1]);
        float bb[5];
        {
            int base = (lane < 16) ? 0 : 5;
#pragma unroll
            for (int g = 0; g < 5; g++) bb[g] = b_b1[base + g];
        }

        int e = slot;
        if (e >= EGn) return;
        int j1 = eig[e];
        int i1 = eig[EGn + e];
        ulonglong2 UA0 = *(const ulonglong2*)(u + (size_t)i1 * SS + ch0);
        ulonglong2 UA1 = *(const ulonglong2*)(u + (size_t)i1 * SS + ch0 + 4);
        ulonglong2 UC0 = *(const ulonglong2*)(u + (size_t)j1 * SS + ch0);
        ulonglong2 UC1 = *(const ulonglong2*)(u + (size_t)j1 * SS + ch0 + 4);
        float db1 = g_db[e];
        int e2 = e + NS;
        int j2 = 0, i2 = 0;
        if (e2 < EGn) { j2 = eig[e2]; i2 = eig[EGn + e2]; }

        while (e < EGn) {
            int e3 = e2 + NS;
            int j3 = 0, i3 = 0;
            if (e3 < EGn) { j3 = eig[e3]; i3 = eig[EGn + e3]; }
            ulonglong2 UB0 = make_ulonglong2(0, 0), UB1 = UB0, UD0 = UB0, UD1 = UB0;
            float db2 = 0.f;
            if (e2 < EGn) {
                UB0 = *(const ulonglong2*)(u + (size_t)i2 * SS + ch0);
                UB1 = *(const ulonglong2*)(u + (size_t)i2 * SS + ch0 + 4);
                UD0 = *(const ulonglong2*)(u + (size_t)j2 * SS + ch0);
                UD1 = *(const ulonglong2*)(u + (size_t)j2 * SS + ch0 + 4);
                db2 = g_db[e2];
            }

            // pre = u_i + u_j + db*wd  (packed pairs)
            ull dbp = f2pk(db1, db1);
            ull prep[4];
            prep[0] = f2fma(dbp, wdp[0], f2add(UA0.x, UC0.x));
            prep[1] = f2fma(dbp, wdp[1], f2add(UA0.y, UC0.y));
            prep[2] = f2fma(dbp, wdp[2], f2add(UA1.x, UC1.x));
            prep[3] = f2fma(dbp, wdp[3], f2add(UA1.y, UC1.y));
            float pre[8];
            f2upk(prep[0], pre[0], pre[1]);
            f2upk(prep[1], pre[2], pre[3]);
            f2upk(prep[2], pre[4], pre[5]);
            f2upk(prep[3], pre[6], pre[7]);

            ull accp[5] = {0ull, 0ull, 0ull, 0ull, 0ull};
#pragma unroll
            for (int k = 0; k < 8; k += 2) {
                // paired-reciprocal silu: one MUFU rcp per 2 channels
                float t0 = __expf(-pre[k]);
                float t1 = __expf(-pre[k + 1]);
                float a0 = 1.0f + t0;
                float a1 = 1.0f + t1;
                float r = __fdividef(1.0f, a0 * a1);
                float hv0 = pre[k] * (r * a1);
                float hv1 = pre[k + 1] * (r * a0);
                ull hvp0 = f2pk(hv0, hv0);
                ull hvp1 = f2pk(hv1, hv1);
#pragma unroll
                for (int m = 0; m < 5; m++) {
                    accp[m] = f2fma(hvp0, wb1p[k][m], accp[m]);
                    accp[m] = f2fma(hvp1, wb1p[k + 1][m], accp[m]);
                }
            }

            float acc[10];
#pragma unroll
            for (int m = 0; m < 5; m++) f2upk(accp[m], acc[2 * m], acc[2 * m + 1]);

#pragma unroll
            for (int o = 0; o < 10; o++)
                acc[o] += __shfl_xor_sync(0xffffffffu, acc[o], 16);
            float v[5];
#pragma unroll
            for (int g = 0; g < 5; g++) v[g] = (lane < 16) ? acc[g] : acc[g + 5];
#pragma unroll
            for (int off = 8; off > 0; off >>= 1) {
#pragma unroll
                for (int g = 0; g < 5; g++)
                    v[g] += __shfl_xor_sync(0xffffffffu, v[g], off);
            }
            if (lane == 0) {
#pragma unroll
                for (int g = 0; g < 5; g++)
                    out[OFF_BP + (size_t)e * 5 + g] = v[g] + bb[g];
            } else if (lane == 16) {
#pragma unroll
                for (int g = 0; g < 5; g++)
                    out[OFF_BE + (size_t)e * 5 + g] = v[g] + bb[g];
            }

            e = e2; i1 = i2; j1 = j2;
            UA0 = UB0; UA1 = UB1; UC0 = UD0; UC1 = UD1;
            db1 = db2;
            e2 = e3; i2 = i3; j2 = j3;
        }
    } else {
        // ---------------- atoms ----------------
        int w = (blk - GBLK) * 4 + (tid >> 5);
        if (w >= NN) return;
        float acc = b_atoms[lane];
        for (int k0 = 0; k0 < SS; k0 += 32) {
            float hv = h3[(size_t)w * SS + k0 + lane];
#pragma unroll
            for (int kk = 0; kk < 32; kk++) {
                float h = __shfl_sync(0xffffffffu, hv, kk);
                acc = fmaf(h, W_atoms[(k0 + kk) * 32 + lane], acc);
            }
        }
        if (lane < NAn) out[OFF_AE + w * NAn + lane] = acc;
        else            out[OFF_AP + w * NAn + (lane - NAn)] = acc;
    }
}

// ============================================================
// Host launcher
// ============================================================
extern "C" void kernel_launch(void* const* d_in, const int* in_sizes, int n_in,
                              void* d_out, int out_size) {
    int iX, iT, iPOS, iWT, iBT, iWA, iBA, iWAT, iBAT, iWSH, iBSH,
        iWB0, iBB0, iWB1, iBB1, iWATM, iBATM, iEIL, iEIG, iBATCH;
    if (in_sizes[3] == 2 * ELn) {
        iX = 0; iT = 1; iPOS = 2; iEIL = 3; iEIG = 4; iBATCH = 6;
        iWT = 7; iBT = 8; iWA = 9; iBA = 10; iWAT = 11; iBAT = 12;
        iWSH = 13; iBSH = 14; iWB0 = 15; iBB0 = 16; iWB1 = 17; iBB1 = 18;
        iWATM = 20; iBATM = 21;
    } else {
        iX = 0; iT = 1; iPOS = 2; iWT = 4; iBT = 5; iWA = 6; iBA = 7;
        iWAT = 8; iBAT = 9; iWSH = 10; iBSH = 11; iWB0 = 12; iBB0 = 13;
        iWB1 = 14; iBB1 = 15; iWATM = 17; iBATM = 18;
        iEIL = 19; iEIG = 20; iBATCH = 21;
    }

    const float* x       = (const float*)d_in[iX];
    const float* t       = (const float*)d_in[iT];
    const float* pos     = (const float*)d_in[iPOS];
    const float* W_time  = (const float*)d_in[iWT];
    const float* b_time  = (const float*)d_in[iBT];
    const float* W_atom  = (const float*)d_in[iWA];
    const float* b_atom  = (const float*)d_in[iBA];
    const float* W_at    = (const float*)d_in[iWAT];
    const float* b_at    = (const float*)d_in[iBAT];
    const float* W_sh    = (const float*)d_in[iWSH];
    const float* b_sh    = (const float*)d_in[iBSH];
    const float* W_b0    = (const float*)d_in[iWB0];
    const float* b_b0    = (const float*)d_in[iBB0];
    const float* W_b1    = (const float*)d_in[iWB1];
    const float* b_b1    = (const float*)d_in[iBB1];
    const float* W_atoms = (const float*)d_in[iWATM];
    const float* b_atoms = (const float*)d_in[iBATM];
    const int* eil       = (const int*)d_in[iEIL];
    const int* eig       = (const int*)d_in[iEIG];
    const int* batch     = (const int*)d_in[iBATCH];
    float* out = (float*)d_out;

    float *bufA, *bufB, *hbias;
    cudaGetSymbolAddress((void**)&bufA, g_bufA);
    cudaGetSymbolAddress((void**)&bufB, g_bufB);
    cudaGetSymbolAddress((void**)&hbias, g_hbias);

    // 1
    k_pre<<<GG + NAn + 1, 256>>>(t, W_time, b_time, b_atom, W_at, b_at, W_atom, b_b0);
    // 2
    k_possum<<<(NN + 255) / 256, 256>>>(pos, batch);
    // 3
    k_center_h2<<<40 + NN, 256>>>(pos, batch, x, out);
    // 4: h3 GEMM + local-edge overlay
    dim3 gg1(2, 157 + LROWS);
    k_gemm64<1, 1><<<gg1, 256>>>(bufA, W_sh, b_sh, bufB, eil, eig, out);
    // 5: u GEMM + global-edge geometry overlay (a_g, rn_g, g_db)
    dim3 gg0(2, 157 + GROWS);
    k_gemm64<0, 2><<<gg0, 256>>>(bufB, W_b0, hbias, bufA, eil, eig, out);
    // 6 — tail: bonds MLP + atoms
    k_tail<<<GBLK + ABLK, 128>>>(eig, bufA, W_b0, W_b1, b_b1,
                                 bufB, W_atoms, b_atoms, out);
}